// round 6
// baseline (speedup 1.0000x reference)
#include <cuda_runtime.h>
#include <cstdint>

#define KDIM 64
#define MDIM 16
#define MP   8                  // m-pairs
#define TPB  128
#define NWARP (TPB / 32)
#define RPW  64                 // rows per warp (2 per lane)
#define RPB  (NWARP * RPW)      // 256 rows per block
#define KC   16                 // k-chunk per pipeline stage
#define NCH  (KDIM / KC)        // 4 chunks
#define TSTRIDE 20              // floats per tile row (16 data + 4 pad) -> conflict-free LDS.128
#define SLICE (RPW * TSTRIDE)   // floats per warp-buffer

typedef unsigned long long u64;
typedef unsigned int u32;

__device__ __forceinline__ u64 pack2(float lo, float hi) {
    u64 r;
    asm("mov.b64 %0, {%1, %2};" : "=l"(r) : "f"(lo), "f"(hi));
    return r;
}

__device__ __forceinline__ void unpack2(u64 v, float& lo, float& hi) {
    asm("mov.b64 {%0, %1}, %2;" : "=f"(lo), "=f"(hi) : "l"(v));
}

__device__ __forceinline__ u64 fma2(u64 a, u64 b, u64 c) {
    u64 d;
    asm("fma.rn.f32x2 %0, %1, %2, %3;" : "=l"(d) : "l"(a), "l"(b), "l"(c));
    return d;
}

__device__ __forceinline__ void cp16(u32 smem_dst, const void* gsrc) {
    asm volatile("cp.async.cg.shared.global [%0], [%1], 16;\n"
                 :: "r"(smem_dst), "l"(gsrc));
}
__device__ __forceinline__ void cp_commit() {
    asm volatile("cp.async.commit_group;\n");
}
template <int N>
__device__ __forceinline__ void cp_wait() {
    asm volatile("cp.async.wait_group %0;\n" :: "n"(N));
}

__global__ __launch_bounds__(TPB, 5)
void dual_compress_kernel(const float* __restrict__ phi_fwd,
                          const float* __restrict__ phi_bwd,
                          const float* __restrict__ alpha_fwd,
                          const float* __restrict__ alpha_bwd,
                          float* __restrict__ out,
                          int V)
{
    // Per-warp double-buffered tiles: 4 warps x 2 bufs x 64 rows x 20 floats = 40,960 B
    __shared__ float tile[NWARP][2][SLICE];
    __shared__ ulonglong2 sw2[KDIM * MP / 2];      // 4,096 B weight table
    u64* swf = (u64*)sw2;

    const int side = blockIdx.y;
    const float* __restrict__ phi   = side ? phi_bwd   : phi_fwd;
    const float* __restrict__ alpha = side ? alpha_bwd : alpha_fwd;
    float* __restrict__ y = out + (size_t)side * (size_t)V * MDIM;

    const int tid  = threadIdx.x;
    const int w    = tid >> 5;
    const int lane = tid & 31;

    const int blockRow = blockIdx.x * RPB;
    const int wbase    = blockRow + w * RPW;

    u32 tb0 = (u32)__cvta_generic_to_shared(&tile[w][0][0]);
    u32 tb1 = (u32)__cvta_generic_to_shared(&tile[w][1][0]);

    // ---- prologue: stage chunks 0 and 1 for this warp's 64-row slab
#pragma unroll
    for (int buf = 0; buf < 2; ++buf) {
        const int ch = buf;
        const u32 tb = buf ? tb1 : tb0;
#pragma unroll
        for (int i = 0; i < (RPW * KC / 4) / 32; ++i) {    // 8 iters
            int idx  = lane + i * 32;
            int row  = idx >> 2;                            // 0..63
            int c4   = idx & 3;
            int grow = min(wbase + row, V - 1);
            cp16(tb + (u32)(row * TSTRIDE + c4 * 4) * 4u,
                 phi + (size_t)grow * KDIM + ch * KC + c4 * 4);
        }
        cp_commit();
    }

    // ---- shared weight table: sw[k][mp] = {exp(alpha[2mp][k]), exp(alpha[2mp+1][k])}
    for (int idx = tid; idx < KDIM * MP; idx += TPB) {
        int k  = idx / MP;
        int mp = idx % MP;
        float w0 = __expf(alpha[(2 * mp)     * KDIM + k]);
        float w1 = __expf(alpha[(2 * mp + 1) * KDIM + k]);
        swf[idx] = pack2(w0, w1);
    }
    __syncthreads();   // the ONLY CTA-wide barrier

    const int r0 = wbase + lane;
    const int r1 = wbase + lane + 32;

    u64 acc0[MP], acc1[MP];
#pragma unroll
    for (int mp = 0; mp < MP; ++mp) { acc0[mp] = 0ull; acc1[mp] = 0ull; }

#pragma unroll
    for (int ch = 0; ch < NCH; ++ch) {
        if (ch == NCH - 1) cp_wait<0>(); else cp_wait<1>();
        __syncwarp();   // all lanes' cps for this chunk complete + visible warp-wide

        const int buf = ch & 1;
        const float4* __restrict__ t0 = (const float4*)&tile[w][buf][lane * TSTRIDE];
        const float4* __restrict__ t1 = (const float4*)&tile[w][buf][(lane + 32) * TSTRIDE];

#pragma unroll
        for (int j4 = 0; j4 < KC / 4; ++j4) {              // 4 iters
            float4 a0 = t0[j4];
            float4 a1 = t1[j4];

            float e0[4], e1[4];
            e0[0] = __expf(a0.x); e0[1] = __expf(a0.y); e0[2] = __expf(a0.z); e0[3] = __expf(a0.w);
            e1[0] = __expf(a1.x); e1[1] = __expf(a1.y); e1[2] = __expf(a1.z); e1[3] = __expf(a1.w);

            const int kbase = ch * KC + j4 * 4;
#pragma unroll
            for (int j = 0; j < 4; ++j) {
                const int k = kbase + j;
                u64 E0 = pack2(e0[j], e0[j]);
                u64 E1 = pack2(e1[j], e1[j]);

                ulonglong2 w01 = sw2[k * 4 + 0];
                ulonglong2 w23 = sw2[k * 4 + 1];
                ulonglong2 w45 = sw2[k * 4 + 2];
                ulonglong2 w67 = sw2[k * 4 + 3];

                acc0[0] = fma2(E0, w01.x, acc0[0]);
                acc1[0] = fma2(E1, w01.x, acc1[0]);
                acc0[1] = fma2(E0, w01.y, acc0[1]);
                acc1[1] = fma2(E1, w01.y, acc1[1]);
                acc0[2] = fma2(E0, w23.x, acc0[2]);
                acc1[2] = fma2(E1, w23.x, acc1[2]);
                acc0[3] = fma2(E0, w23.y, acc0[3]);
                acc1[3] = fma2(E1, w23.y, acc1[3]);
                acc0[4] = fma2(E0, w45.x, acc0[4]);
                acc1[4] = fma2(E1, w45.x, acc1[4]);
                acc0[5] = fma2(E0, w45.y, acc0[5]);
                acc1[5] = fma2(E1, w45.y, acc1[5]);
                acc0[6] = fma2(E0, w67.x, acc0[6]);
                acc1[6] = fma2(E1, w67.x, acc1[6]);
                acc0[7] = fma2(E0, w67.y, acc0[7]);
                acc1[7] = fma2(E1, w67.y, acc1[7]);
            }
        }

        // restage this warp's just-consumed buffer with chunk ch+2
        if (ch + 2 < NCH) {
            __syncwarp();   // every lane done reading tile[w][buf]
            const int nch = ch + 2;
            const u32 tb = buf ? tb1 : tb0;
#pragma unroll
            for (int i = 0; i < (RPW * KC / 4) / 32; ++i) {
                int idx  = lane + i * 32;
                int row  = idx >> 2;
                int c4   = idx & 3;
                int grow = min(wbase + row, V - 1);
                cp16(tb + (u32)(row * TSTRIDE + c4 * 4) * 4u,
                     phi + (size_t)grow * KDIM + nch * KC + c4 * 4);
            }
            cp_commit();
        }
    }

    // ---- epilogue: y = log(sum)
    float y0[MDIM], y1[MDIM];
#pragma unroll
    for (int mp = 0; mp < MP; ++mp) {
        float s0a, s0b, s1a, s1b;
        unpack2(acc0[mp], s0a, s0b);
        unpack2(acc1[mp], s1a, s1b);
        y0[2 * mp] = __logf(s0a); y0[2 * mp + 1] = __logf(s0b);
        y1[2 * mp] = __logf(s1a); y1[2 * mp + 1] = __logf(s1b);
    }

    if (r0 < V) {
        float4* o = (float4*)(y + (size_t)r0 * MDIM);
        o[0] = make_float4(y0[0],  y0[1],  y0[2],  y0[3]);
        o[1] = make_float4(y0[4],  y0[5],  y0[6],  y0[7]);
        o[2] = make_float4(y0[8],  y0[9],  y0[10], y0[11]);
        o[3] = make_float4(y0[12], y0[13], y0[14], y0[15]);
    }
    if (r1 < V) {
        float4* o = (float4*)(y + (size_t)r1 * MDIM);
        o[0] = make_float4(y1[0],  y1[1],  y1[2],  y1[3]);
        o[1] = make_float4(y1[4],  y1[5],  y1[6],  y1[7]);
        o[2] = make_float4(y1[8],  y1[9],  y1[10], y1[11]);
        o[3] = make_float4(y1[12], y1[13], y1[14], y1[15]);
    }
}

extern "C" void kernel_launch(void* const* d_in, const int* in_sizes, int n_in,
                              void* d_out, int out_size)
{
    const float* d_out_t   = (const float*)d_in[0];  // (V, 64) fwd phi
    const float* d_in_t    = (const float*)d_in[1];  // (V, 64) bwd phi
    const float* alpha_fwd = (const float*)d_in[2];  // (16, 64)
    const float* alpha_bwd = (const float*)d_in[3];  // (16, 64)
    float* out = (float*)d_out;                      // [y_fwd (V,16) | y_bwd (V,16)]

    const int V = in_sizes[0] / KDIM;

    dim3 grid((V + RPB - 1) / RPB, 2);
    dual_compress_kernel<<<grid, TPB>>>(d_out_t, d_in_t, alpha_fwd, alpha_bwd, out, V);
}